// round 6
// baseline (speedup 1.0000x reference)
#include <cuda_runtime.h>
#include <cuda_bf16.h>
#include <cstdint>

#define Bsz 256
#define Hd  512
#define N3  1536
#define KTOT 1024

// ---------------- scratch (no allocs allowed) ----------------
__device__ float g_projA[Bsz * N3];  // K-half 0 partial (+bias)
__device__ float g_projB[Bsz * N3];  // K-half 1 partial
__device__ float g_hn[Bsz * Hd];     // assoc @ Rh
__device__ int   g_cnt[Bsz];         // per-batch arrival counters (self-resetting)
__device__ __nv_bfloat16 g_Ahi[Bsz * KTOT];
__device__ __nv_bfloat16 g_Alo[Bsz * KTOT];
__device__ __nv_bfloat16 g_Bhi[N3 * KTOT];
__device__ __nv_bfloat16 g_Blo[N3 * KTOT];

__device__ __forceinline__ uint32_t smem_to_u32(const void* p) {
    uint32_t a;
    asm("{ .reg .u64 t; cvta.to.shared.u64 t, %1; cvt.u32.u64 %0, t; }"
        : "=r"(a) : "l"(p));
    return a;
}
__device__ __forceinline__ void cp16(uint32_t s, const void* g) {
    asm volatile("cp.async.cg.shared.global [%0], [%1], 16;"
                 :: "r"(s), "l"(g) : "memory");
}
__device__ __forceinline__ void ldsm_x4(uint32_t* r, uint32_t addr) {
    asm volatile("ldmatrix.sync.aligned.m8n8.x4.shared.b16 {%0,%1,%2,%3}, [%4];"
                 : "=r"(r[0]), "=r"(r[1]), "=r"(r[2]), "=r"(r[3]) : "r"(addr));
}
__device__ __forceinline__ void mma_bf16(float* c, const uint32_t* a, const uint32_t* b) {
    asm volatile(
        "mma.sync.aligned.m16n8k16.row.col.f32.bf16.bf16.f32 "
        "{%0,%1,%2,%3}, {%4,%5,%6,%7}, {%8,%9}, {%0,%1,%2,%3};"
        : "+f"(c[0]), "+f"(c[1]), "+f"(c[2]), "+f"(c[3])
        : "r"(a[0]), "r"(a[1]), "r"(a[2]), "r"(a[3]), "r"(b[0]), "r"(b[1]));
}
// swizzled byte offset within a 64-row x 64-byte tile (4KB)
__device__ __forceinline__ uint32_t sw_off(int row, int chunk) {
    return (uint32_t)(row * 64 + ((chunk ^ ((row >> 1) & 3)) << 4));
}

// ---------------------------------------------------------------------------
// Kernel 0: fp32 -> (hi, lo) bf16 split. 8 elems/thread, uniform block routing.
// Blocks [0,128): A (inputs|hidden). Blocks [128,896): B (W_ih|W_hh).
// ---------------------------------------------------------------------------
__global__ __launch_bounds__(256) void convert_kernel(
    const float* __restrict__ inputs, const float* __restrict__ hidden,
    const float* __restrict__ W_ih,   const float* __restrict__ W_hh)
{
    union U8 { uint4 u; __nv_bfloat162 b[4]; };
    const int tid = threadIdx.x;
    const float* src;
    __nv_bfloat16 *dhi, *dlo;
    size_t e;
    if (blockIdx.x < 128) {
        int gid = blockIdx.x * 256 + tid;          // [0, 32768)
        e = (size_t)gid * 8;
        int m = (int)(e >> 10), k = (int)(e & 1023);
        src = (k < 512) ? inputs + (size_t)m * 512 + k
                        : hidden + (size_t)m * 512 + (k - 512);
        dhi = g_Ahi; dlo = g_Alo;
    } else {
        int gid = (blockIdx.x - 128) * 256 + tid;  // [0, 196608)
        e = (size_t)gid * 8;
        int n = (int)(e >> 10), k = (int)(e & 1023);
        src = (k < 512) ? W_ih + (size_t)n * 512 + k
                        : W_hh + (size_t)n * 512 + (k - 512);
        dhi = g_Bhi; dlo = g_Blo;
    }
    float4 v0 = *(const float4*)src;
    float4 v1 = *(const float4*)(src + 4);
    float f[8] = {v0.x, v0.y, v0.z, v0.w, v1.x, v1.y, v1.z, v1.w};
    U8 hi, lo;
    #pragma unroll
    for (int i = 0; i < 4; i++) {
        __nv_bfloat16 h0 = __float2bfloat16(f[2 * i]);
        __nv_bfloat16 h1 = __float2bfloat16(f[2 * i + 1]);
        hi.b[i] = __nv_bfloat162(h0, h1);
        lo.b[i] = __nv_bfloat162(
            __float2bfloat16(f[2 * i]     - __bfloat162float(h0)),
            __float2bfloat16(f[2 * i + 1] - __bfloat162float(h1)));
    }
    *(uint4*)(dhi + e) = hi.u;
    *(uint4*)(dlo + e) = lo.u;
}

// ---------------------------------------------------------------------------
// Kernel 1: HMMA bf16 split GEMM, K-split x2 (blockIdx.z = K half).
// CTA 64x64, 4 warps (2x2), 16 K-chunks of 32, cp.async double buffer.
// z=0 -> g_projA (+bias), z=1 -> g_projB.
// ---------------------------------------------------------------------------
#define AHI_OFF 0
#define ALO_OFF 4096
#define BHI_OFF 8192
#define BLO_OFF 12288
#define NCHUNK  16

__global__ __launch_bounds__(128) void gemm_mma_kernel(
    const float* __restrict__ b_ih, const float* __restrict__ b_hh)
{
    __shared__ __align__(1024) char smem[2][16384];
    __shared__ float sbias[64];

    const int tid = threadIdx.x;
    const int wid = tid >> 5, lane = tid & 31;
    const int wm = wid & 1, wn = wid >> 1;
    const int bn = blockIdx.x * 64, bm = blockIdx.y * 64;
    const int kz = blockIdx.z;
    const int kbase = kz * 512;

    if (kz == 0 && tid < 64) sbias[tid] = b_ih[bn + tid] + b_hh[bn + tid];

    const uint32_t sb0 = smem_to_u32(&smem[0][0]);
    const uint32_t sb1 = smem_to_u32(&smem[1][0]);

    const int c0row = tid >> 2,         c0chk = tid & 3;
    const int c1row = (tid + 128) >> 2, c1chk = (tid + 128) & 3;
    const uint32_t so0 = sw_off(c0row, c0chk);
    const uint32_t so1 = sw_off(c1row, c1chk);

    auto prefetch = [&](int ch) {
        const uint32_t sbuf = (ch & 1) ? sb1 : sb0;
        const int k0 = kbase + ch * 32;
        size_t gA0 = (size_t)(bm + c0row) * KTOT + k0 + c0chk * 8;
        size_t gA1 = (size_t)(bm + c1row) * KTOT + k0 + c1chk * 8;
        size_t gB0 = (size_t)(bn + c0row) * KTOT + k0 + c0chk * 8;
        size_t gB1 = (size_t)(bn + c1row) * KTOT + k0 + c1chk * 8;
        cp16(sbuf + AHI_OFF + so0, g_Ahi + gA0);
        cp16(sbuf + AHI_OFF + so1, g_Ahi + gA1);
        cp16(sbuf + ALO_OFF + so0, g_Alo + gA0);
        cp16(sbuf + ALO_OFF + so1, g_Alo + gA1);
        cp16(sbuf + BHI_OFF + so0, g_Bhi + gB0);
        cp16(sbuf + BHI_OFF + so1, g_Bhi + gB1);
        cp16(sbuf + BLO_OFF + so0, g_Blo + gB0);
        cp16(sbuf + BLO_OFF + so1, g_Blo + gB1);
        asm volatile("cp.async.commit_group;" ::: "memory");
    };

    float acc[2][4][4];
    #pragma unroll
    for (int mi = 0; mi < 2; mi++)
        #pragma unroll
        for (int ni = 0; ni < 4; ni++)
            #pragma unroll
            for (int q = 0; q < 4; q++) acc[mi][ni][q] = 0.0f;

    const int lArow = wm * 32 + (lane & 15);
    const int lAhalf = lane >> 4;
    const int lBrow = wn * 32 + ((lane >> 4) << 3) + (lane & 7);
    const int lBhalf = (lane >> 3) & 1;

    prefetch(0);
    prefetch(1);

    for (int ch = 0; ch < NCHUNK; ch++) {
        if (ch < NCHUNK - 1) { asm volatile("cp.async.wait_group 1;" ::: "memory"); }
        else                 { asm volatile("cp.async.wait_group 0;" ::: "memory"); }
        __syncthreads();

        const uint32_t sbuf = (ch & 1) ? sb1 : sb0;

        #pragma unroll
        for (int ks = 0; ks < 2; ks++) {
            uint32_t ahi[2][4], alo[2][4], bhi[8], blo[8];
            #pragma unroll
            for (int mi = 0; mi < 2; mi++) {
                int row = lArow + mi * 16;
                uint32_t so = sw_off(row, ks * 2 + lAhalf);
                ldsm_x4(ahi[mi], sbuf + AHI_OFF + so);
                ldsm_x4(alo[mi], sbuf + ALO_OFF + so);
            }
            #pragma unroll
            for (int nj = 0; nj < 2; nj++) {
                int row = lBrow + nj * 16;
                uint32_t so = sw_off(row, ks * 2 + lBhalf);
                ldsm_x4(&bhi[nj * 4], sbuf + BHI_OFF + so);
                ldsm_x4(&blo[nj * 4], sbuf + BLO_OFF + so);
            }
            #pragma unroll
            for (int mi = 0; mi < 2; mi++)
                #pragma unroll
                for (int ni = 0; ni < 4; ni++) {
                    mma_bf16(acc[mi][ni], ahi[mi], &bhi[ni * 2]);
                    mma_bf16(acc[mi][ni], ahi[mi], &blo[ni * 2]);
                    mma_bf16(acc[mi][ni], alo[mi], &bhi[ni * 2]);
                }
        }
        __syncthreads();
        if (ch + 2 < NCHUNK) prefetch(ch + 2);
    }

    float* pbuf = kz ? g_projB : g_projA;
    const int g = lane >> 2, tg = lane & 3;
    #pragma unroll
    for (int mi = 0; mi < 2; mi++) {
        #pragma unroll
        for (int ni = 0; ni < 4; ni++) {
            int colo = wn * 32 + ni * 8 + tg * 2;
            int col = bn + colo;
            float bv0 = kz ? 0.0f : sbias[colo];
            float bv1 = kz ? 0.0f : sbias[colo + 1];
            int row0 = bm + wm * 32 + mi * 16 + g;
            float2 v0 = make_float2(acc[mi][ni][0] + bv0, acc[mi][ni][1] + bv1);
            float2 v1 = make_float2(acc[mi][ni][2] + bv0, acc[mi][ni][3] + bv1);
            *(float2*)(pbuf + (size_t)row0 * N3 + col) = v0;
            *(float2*)(pbuf + (size_t)(row0 + 8) * N3 + col) = v1;
        }
    }
}

// combined proj load (sum of two K-half partials)
__device__ __forceinline__ float4 ldproj(const float* a, const float* b, int i4) {
    float4 u = ((const float4*)a)[i4];
    float4 v = ((const float4*)b)[i4];
    u.x += v.x; u.y += v.y; u.z += v.z; u.w += v.w;
    return u;
}

// ---------------------------------------------------------------------------
// Kernel 2 (FUSED, 4 CTAs per batch): grid (4, 256), 256 threads.
//   phase 1 (redundant per CTA): dots -> alpha,beta; Rh in smem
//   phase 2: 128 assoc rows per CTA (8 warps x 16), __ldcs, write g_hn
//   phase 3: last-arriving CTA per batch finalizes + resets counter
// ---------------------------------------------------------------------------
__global__ __launch_bounds__(256) void fused_mv_kernel(
    const float* __restrict__ hidden, const float* __restrict__ assoc,
    float* __restrict__ out)
{
    __shared__ float sRh[Hd];
    __shared__ float red[5][4];
    __shared__ float s_ab[2];
    __shared__ float nred[4];
    __shared__ float s_inv;
    __shared__ int s_last;

    const int q = blockIdx.x, b = blockIdx.y;
    const int t = threadIdx.x;
    const int lane = t & 31, warp = t >> 5;
    const float* bA = g_projA + (size_t)b * N3;
    const float* bB = g_projB + (size_t)b * N3;

    // ---- phase 1: dots (threads 0..127) ----
    if (t < 128) {
        float4 x = ldproj(bA + 2 * Hd, bB + 2 * Hd, t);
        float4 r = ldproj(bA + Hd,     bB + Hd,     t);
        float4 h = ((const float4*)(hidden + (size_t)b * Hd))[t];
        float vals[5];
        vals[0] = x.x * x.x + x.y * x.y + x.z * x.z + x.w * x.w;
        vals[1] = r.x * r.x + r.y * r.y + r.z * r.z + r.w * r.w;
        vals[2] = x.x * r.x + x.y * r.y + x.z * r.z + x.w * r.w;
        vals[3] = x.x * h.x + x.y * h.y + x.z * h.z + x.w * h.w;
        vals[4] = r.x * h.x + r.y * h.y + r.z * h.z + r.w * h.w;
        #pragma unroll
        for (int i = 0; i < 5; i++) {
            float v = vals[i];
            #pragma unroll
            for (int o = 16; o; o >>= 1) v += __shfl_down_sync(0xffffffffu, v, o);
            if (!lane) red[i][warp] = v;
        }
    }
    __syncthreads();
    if (t == 0) {
        float S[5];
        #pragma unroll
        for (int i = 0; i < 5; i++)
            S[i] = red[i][0] + red[i][1] + red[i][2] + red[i][3];
        const float eps = 1e-12f;
        float nx = fmaxf(sqrtf(S[0]), eps);
        float nr = fmaxf(sqrtf(S[1]), eps);
        float c  = S[2] / (nx * nr);
        float s  = sqrtf(fmaxf(1.0f - c * c, 0.0f));
        float g  = S[2] / (nx * nx);
        float vn2 = S[1] - 2.0f * g * S[2] + g * g * S[0];
        float nv = fmaxf(sqrtf(fmaxf(vn2, 0.0f)), eps);
        float uh = S[3] / nx;
        float vh = (S[4] - g * S[3]) / nv;
        float P = (c - 1.0f) * uh - s * vh;
        float Q = (c - 1.0f) * vh + s * uh;
        s_ab[0] = P / nx - Q * g / nv;
        s_ab[1] = Q / nv;
    }
    __syncthreads();
    if (t < 128) {
        float4 x = ldproj(bA + 2 * Hd, bB + 2 * Hd, t);
        float4 r = ldproj(bA + Hd,     bB + Hd,     t);
        float4 h = ((const float4*)(hidden + (size_t)b * Hd))[t];
        float al = s_ab[0], be = s_ab[1];
        float4 o;
        o.x = h.x + al * x.x + be * r.x;
        o.y = h.y + al * x.y + be * r.y;
        o.z = h.z + al * x.z + be * r.z;
        o.w = h.w + al * x.w + be * r.w;
        ((float4*)sRh)[t] = o;
    }
    __syncthreads();

    // ---- phase 2: 128 rows = 8 warps x 16 rows, streaming ----
    const int rowbase = q * 128;
    #pragma unroll 1
    for (int rr = 0; rr < 16; rr++) {
        int row = rowbase + warp * 16 + rr;
        const float4* p = (const float4*)(assoc + ((size_t)b * Hd + row) * Hd);
        float sum = 0.0f;
        #pragma unroll
        for (int it = 0; it < 4; it++) {
            float4 v = __ldcs(p + lane + it * 32);
            int j = (lane + it * 32) << 2;
            sum += v.x * sRh[j] + v.y * sRh[j + 1] + v.z * sRh[j + 2] + v.w * sRh[j + 3];
        }
        #pragma unroll
        for (int o = 16; o; o >>= 1) sum += __shfl_down_sync(0xffffffffu, sum, o);
        if (!lane) g_hn[(size_t)b * Hd + row] = sum;
    }

    // ---- arrival protocol: last CTA per batch finalizes ----
    __threadfence();
    __syncthreads();
    if (t == 0) {
        int old = atomicAdd(&g_cnt[b], 1);
        s_last = (old == 3);
    }
    __syncthreads();
    if (!s_last) return;
    __threadfence();   // acquire side: see all 4 CTAs' g_hn writes

    // ---- phase 3: finalize ----
    float4 pre;
    if (t < 128) {
        float4 ug = ldproj(bA, bB, t);
        float4 x  = ldproj(bA + 2 * Hd, bB + 2 * Hd, t);
        float4 h  = ((const float4*)(hidden + (size_t)b * Hd))[t];
        float4 hn = ((const float4*)(g_hn + (size_t)b * Hd))[t];
        pre.x = ug.x * h.x + (1.0f - ug.x) * fmaxf(hn.x + x.x, 0.0f);
        pre.y = ug.y * h.y + (1.0f - ug.y) * fmaxf(hn.y + x.y, 0.0f);
        pre.z = ug.z * h.z + (1.0f - ug.z) * fmaxf(hn.z + x.z, 0.0f);
        pre.w = ug.w * h.w + (1.0f - ug.w) * fmaxf(hn.w + x.w, 0.0f);
        float ss = pre.x * pre.x + pre.y * pre.y + pre.z * pre.z + pre.w * pre.w;
        #pragma unroll
        for (int o = 16; o; o >>= 1) ss += __shfl_down_sync(0xffffffffu, ss, o);
        if (!lane) nred[warp] = ss;
    }
    __syncthreads();
    if (t == 0) {
        float n = sqrtf(nred[0] + nred[1] + nred[2] + nred[3]);
        s_inv = 1.0f / fmaxf(n, 1e-12f);
        g_cnt[b] = 0;   // reset for next graph replay
    }
    __syncthreads();
    if (t < 128) {
        float inv = s_inv;
        float4 o4;
        o4.x = pre.x * inv; o4.y = pre.y * inv;
        o4.z = pre.z * inv; o4.w = pre.w * inv;
        ((float4*)out)[b * (Hd / 4) + t] = o4;
    }
}

extern "C" void kernel_launch(void* const* d_in, const int* in_sizes, int n_in,
                              void* d_out, int out_size)
{
    const float* inputs = (const float*)d_in[0];
    const float* hidden = (const float*)d_in[1];
    const float* assoc  = (const float*)d_in[2];
    const float* W_ih   = (const float*)d_in[3];
    const float* b_ih   = (const float*)d_in[4];
    const float* W_hh   = (const float*)d_in[5];
    const float* b_hh   = (const float*)d_in[6];
    float* out = (float*)d_out;

    convert_kernel<<<896, 256>>>(inputs, hidden, W_ih, W_hh);
    gemm_mma_kernel<<<dim3(N3 / 64, Bsz / 64, 2), 128>>>(b_ih, b_hh);
    fused_mv_kernel<<<dim3(4, Bsz), 256>>>(hidden, assoc, out);
}

// round 7
// speedup vs baseline: 1.1028x; 1.1028x over previous
#include <cuda_runtime.h>
#include <cuda_bf16.h>
#include <cstdint>

#define Bsz 256
#define Hd  512
#define N3  1536
#define KTOT 1024

// ---------------- scratch (no allocs allowed) ----------------
__device__ float g_proj4[4][Bsz * N3];  // 4 K-split partials ([0] carries bias)
__device__ float g_hn[Bsz * Hd];        // assoc @ Rh
__device__ int   g_cnt[Bsz];            // per-batch arrival counters (self-reset)

__device__ __forceinline__ uint32_t smem_to_u32(const void* p) {
    uint32_t a;
    asm("{ .reg .u64 t; cvta.to.shared.u64 t, %1; cvt.u32.u64 %0, t; }"
        : "=r"(a) : "l"(p));
    return a;
}
__device__ __forceinline__ void ldsm_x4(uint32_t* r, uint32_t addr) {
    asm volatile("ldmatrix.sync.aligned.m8n8.x4.shared.b16 {%0,%1,%2,%3}, [%4];"
                 : "=r"(r[0]), "=r"(r[1]), "=r"(r[2]), "=r"(r[3]) : "r"(addr));
}
__device__ __forceinline__ void mma_bf16(float* c, const uint32_t* a, const uint32_t* b) {
    asm volatile(
        "mma.sync.aligned.m16n8k16.row.col.f32.bf16.bf16.f32 "
        "{%0,%1,%2,%3}, {%4,%5,%6,%7}, {%8,%9}, {%0,%1,%2,%3};"
        : "+f"(c[0]), "+f"(c[1]), "+f"(c[2]), "+f"(c[3])
        : "r"(a[0]), "r"(a[1]), "r"(a[2]), "r"(a[3]), "r"(b[0]), "r"(b[1]));
}
// swizzled byte offset within a 64-row x 64-byte tile (4KB)
__device__ __forceinline__ uint32_t sw_off(int row, int chunk) {
    return (uint32_t)(row * 64 + ((chunk ^ ((row >> 1) & 3)) << 4));
}
// split 8 fp32 -> 8 bf16 hi + 8 bf16 lo (packed 16B each)
__device__ __forceinline__ void cvt8(const float4& u, const float4& v,
                                     uint4& hi, uint4& lo) {
    union P { uint4 q; __nv_bfloat162 b[4]; } ph, pl;
    float f[8] = {u.x, u.y, u.z, u.w, v.x, v.y, v.z, v.w};
    #pragma unroll
    for (int i = 0; i < 4; i++) {
        __nv_bfloat16 h0 = __float2bfloat16(f[2 * i]);
        __nv_bfloat16 h1 = __float2bfloat16(f[2 * i + 1]);
        ph.b[i] = __nv_bfloat162(h0, h1);
        pl.b[i] = __nv_bfloat162(
            __float2bfloat16(f[2 * i]     - __bfloat162float(h0)),
            __float2bfloat16(f[2 * i + 1] - __bfloat162float(h1)));
    }
    hi = ph.q; lo = pl.q;
}

// ---------------------------------------------------------------------------
// Kernel 1: HMMA bf16 split GEMM with FUSED fp32->bf16 conversion.
// 4-way K-split (blockIdx.z): kz in {0,1} -> inputs/W_ih, {2,3} -> hidden/W_hh.
// CTA 64x64, 4 warps, 8 K-chunks of 32. LDG fp32 -> reg split -> STS bf16.
// ---------------------------------------------------------------------------
#define AHI_OFF 0
#define ALO_OFF 4096
#define BHI_OFF 8192
#define BLO_OFF 12288
#define NCHUNK  8

__global__ __launch_bounds__(128) void gemm_mma_kernel(
    const float* __restrict__ inputs, const float* __restrict__ hidden,
    const float* __restrict__ W_ih,   const float* __restrict__ W_hh,
    const float* __restrict__ b_ih,   const float* __restrict__ b_hh)
{
    __shared__ __align__(1024) char smem[2][16384];
    __shared__ float sbias[64];

    const int tid = threadIdx.x;
    const int wid = tid >> 5, lane = tid & 31;
    const int wm = wid & 1, wn = wid >> 1;
    const int bn = blockIdx.x * 64, bm = blockIdx.y * 64;
    const int kz = blockIdx.z;

    const float* Abase = (kz < 2 ? inputs : hidden) + (kz & 1) * 256;
    const float* Bbase = (kz < 2 ? W_ih   : W_hh)   + (kz & 1) * 256;

    if (kz == 0 && tid < 64) sbias[tid] = b_ih[bn + tid] + b_hh[bn + tid];

    const uint32_t sb0 = smem_to_u32(&smem[0][0]);
    const uint32_t sb1 = smem_to_u32(&smem[1][0]);

    // two granules per thread per tile: (row, 16B-chunk-col)
    const int r0 = tid >> 2,         c0 = tid & 3;
    const int r1 = (tid + 128) >> 2, c1 = (tid + 128) & 3;
    const uint32_t so0 = sw_off(r0, c0);
    const uint32_t so1 = sw_off(r1, c1);

    float4 rA[4], rB[4];   // staging: [g0.lo4, g0.hi4, g1.lo4, g1.hi4]

    auto ldg_chunk = [&](int ch) {
        const int k0 = ch * 32;
        const float* a0 = Abase + (size_t)(bm + r0) * 512 + k0 + c0 * 8;
        const float* a1 = Abase + (size_t)(bm + r1) * 512 + k0 + c1 * 8;
        const float* b0 = Bbase + (size_t)(bn + r0) * 512 + k0 + c0 * 8;
        const float* b1 = Bbase + (size_t)(bn + r1) * 512 + k0 + c1 * 8;
        rA[0] = *(const float4*)a0; rA[1] = *(const float4*)(a0 + 4);
        rA[2] = *(const float4*)a1; rA[3] = *(const float4*)(a1 + 4);
        rB[0] = *(const float4*)b0; rB[1] = *(const float4*)(b0 + 4);
        rB[2] = *(const float4*)b1; rB[3] = *(const float4*)(b1 + 4);
    };
    auto sts_chunk = [&](int bsel) {
        char* buf = smem[bsel];
        uint4 hi, lo;
        cvt8(rA[0], rA[1], hi, lo);
        *(uint4*)(buf + AHI_OFF + so0) = hi; *(uint4*)(buf + ALO_OFF + so0) = lo;
        cvt8(rA[2], rA[3], hi, lo);
        *(uint4*)(buf + AHI_OFF + so1) = hi; *(uint4*)(buf + ALO_OFF + so1) = lo;
        cvt8(rB[0], rB[1], hi, lo);
        *(uint4*)(buf + BHI_OFF + so0) = hi; *(uint4*)(buf + BLO_OFF + so0) = lo;
        cvt8(rB[2], rB[3], hi, lo);
        *(uint4*)(buf + BHI_OFF + so1) = hi; *(uint4*)(buf + BLO_OFF + so1) = lo;
    };

    float acc[2][4][4];
    #pragma unroll
    for (int mi = 0; mi < 2; mi++)
        #pragma unroll
        for (int ni = 0; ni < 4; ni++)
            #pragma unroll
            for (int q = 0; q < 4; q++) acc[mi][ni][q] = 0.0f;

    const int lArow = wm * 32 + (lane & 15);
    const int lAhalf = lane >> 4;
    const int lBrow = wn * 32 + ((lane >> 4) << 3) + (lane & 7);
    const int lBhalf = (lane >> 3) & 1;

    ldg_chunk(0);

    for (int ch = 0; ch < NCHUNK; ch++) {
        sts_chunk(ch & 1);
        if (ch + 1 < NCHUNK) ldg_chunk(ch + 1);
        __syncthreads();

        const uint32_t sbuf = (ch & 1) ? sb1 : sb0;
        #pragma unroll
        for (int ks = 0; ks < 2; ks++) {
            uint32_t ahi[2][4], alo[2][4], bhi[8], blo[8];
            #pragma unroll
            for (int mi = 0; mi < 2; mi++) {
                int row = lArow + mi * 16;
                uint32_t so = sw_off(row, ks * 2 + lAhalf);
                ldsm_x4(ahi[mi], sbuf + AHI_OFF + so);
                ldsm_x4(alo[mi], sbuf + ALO_OFF + so);
            }
            #pragma unroll
            for (int nj = 0; nj < 2; nj++) {
                int row = lBrow + nj * 16;
                uint32_t so = sw_off(row, ks * 2 + lBhalf);
                ldsm_x4(&bhi[nj * 4], sbuf + BHI_OFF + so);
                ldsm_x4(&blo[nj * 4], sbuf + BLO_OFF + so);
            }
            #pragma unroll
            for (int mi = 0; mi < 2; mi++)
                #pragma unroll
                for (int ni = 0; ni < 4; ni++) {
                    mma_bf16(acc[mi][ni], ahi[mi], &bhi[ni * 2]);
                    mma_bf16(acc[mi][ni], ahi[mi], &blo[ni * 2]);
                    mma_bf16(acc[mi][ni], alo[mi], &bhi[ni * 2]);
                }
        }
        __syncthreads();
    }

    float* pbuf = g_proj4[kz];
    const int g = lane >> 2, tg = lane & 3;
    #pragma unroll
    for (int mi = 0; mi < 2; mi++) {
        #pragma unroll
        for (int ni = 0; ni < 4; ni++) {
            int colo = wn * 32 + ni * 8 + tg * 2;
            int col = bn + colo;
            float bv0 = (kz == 0) ? sbias[colo]     : 0.0f;
            float bv1 = (kz == 0) ? sbias[colo + 1] : 0.0f;
            int row0 = bm + wm * 32 + mi * 16 + g;
            float2 v0 = make_float2(acc[mi][ni][0] + bv0, acc[mi][ni][1] + bv1);
            float2 v1 = make_float2(acc[mi][ni][2] + bv0, acc[mi][ni][3] + bv1);
            *(float2*)(pbuf + (size_t)row0 * N3 + col) = v0;
            *(float2*)(pbuf + (size_t)(row0 + 8) * N3 + col) = v1;
        }
    }
}

// sum of 4 K-split partials; eo = element offset within proj array, t = float4 idx
__device__ __forceinline__ float4 ldproj4(size_t eo, int t) {
    float4 s = ((const float4*)(g_proj4[0] + eo))[t];
    #pragma unroll
    for (int p = 1; p < 4; p++) {
        float4 v = ((const float4*)(g_proj4[p] + eo))[t];
        s.x += v.x; s.y += v.y; s.z += v.z; s.w += v.w;
    }
    return s;
}

// ---------------------------------------------------------------------------
// Kernel 2 (FUSED, 8 CTAs per batch): grid (8, 256), 256 threads.
//   phase 1 (redundant per CTA, register-resident): dots -> alpha,beta; Rh
//   phase 2: 64 assoc rows per CTA (8 warps x 8), __ldcs, write g_hn
//   phase 3: last-arriving CTA per batch finalizes + resets counter
// ---------------------------------------------------------------------------
__global__ __launch_bounds__(256) void fused_mv_kernel(
    const float* __restrict__ hidden, const float* __restrict__ assoc,
    float* __restrict__ out)
{
    __shared__ float sRh[Hd];
    __shared__ float red[5][4];
    __shared__ float s_ab[2];
    __shared__ float nred[4];
    __shared__ float s_inv;
    __shared__ int s_last;

    const int q = blockIdx.x, b = blockIdx.y;
    const int t = threadIdx.x;
    const int lane = t & 31, warp = t >> 5;
    const size_t prow = (size_t)b * N3;

    // ---- phase 1: dots (threads 0..127), x/r/h stay in registers ----
    float4 x, r, h;
    if (t < 128) {
        x = ldproj4(prow + 2 * Hd, t);
        r = ldproj4(prow + Hd,     t);
        h = ((const float4*)(hidden + (size_t)b * Hd))[t];
        float vals[5];
        vals[0] = x.x * x.x + x.y * x.y + x.z * x.z + x.w * x.w;
        vals[1] = r.x * r.x + r.y * r.y + r.z * r.z + r.w * r.w;
        vals[2] = x.x * r.x + x.y * r.y + x.z * r.z + x.w * r.w;
        vals[3] = x.x * h.x + x.y * h.y + x.z * h.z + x.w * h.w;
        vals[4] = r.x * h.x + r.y * h.y + r.z * h.z + r.w * h.w;
        #pragma unroll
        for (int i = 0; i < 5; i++) {
            float v = vals[i];
            #pragma unroll
            for (int o = 16; o; o >>= 1) v += __shfl_down_sync(0xffffffffu, v, o);
            if (!lane) red[i][warp] = v;
        }
    }
    __syncthreads();
    if (t == 0) {
        float S[5];
        #pragma unroll
        for (int i = 0; i < 5; i++)
            S[i] = red[i][0] + red[i][1] + red[i][2] + red[i][3];
        const float eps = 1e-12f;
        float nx = fmaxf(sqrtf(S[0]), eps);
        float nr = fmaxf(sqrtf(S[1]), eps);
        float c  = S[2] / (nx * nr);
        float s  = sqrtf(fmaxf(1.0f - c * c, 0.0f));
        float g  = S[2] / (nx * nx);
        float vn2 = S[1] - 2.0f * g * S[2] + g * g * S[0];
        float nv = fmaxf(sqrtf(fmaxf(vn2, 0.0f)), eps);
        float uh = S[3] / nx;
        float vh = (S[4] - g * S[3]) / nv;
        float P = (c - 1.0f) * uh - s * vh;
        float Q = (c - 1.0f) * vh + s * uh;
        s_ab[0] = P / nx - Q * g / nv;
        s_ab[1] = Q / nv;
    }
    __syncthreads();
    if (t < 128) {
        float al = s_ab[0], be = s_ab[1];
        float4 o;
        o.x = h.x + al * x.x + be * r.x;
        o.y = h.y + al * x.y + be * r.y;
        o.z = h.z + al * x.z + be * r.z;
        o.w = h.w + al * x.w + be * r.w;
        ((float4*)sRh)[t] = o;
    }
    __syncthreads();

    // ---- phase 2: 64 rows = 8 warps x 8 rows, streaming ----
    const int rowbase = q * 64;
    #pragma unroll 1
    for (int rr = 0; rr < 8; rr++) {
        int row = rowbase + warp * 8 + rr;
        const float4* p = (const float4*)(assoc + ((size_t)b * Hd + row) * Hd);
        float sum = 0.0f;
        #pragma unroll
        for (int it = 0; it < 4; it++) {
            float4 v = __ldcs(p + lane + it * 32);
            int j = (lane + it * 32) << 2;
            sum += v.x * sRh[j] + v.y * sRh[j + 1] + v.z * sRh[j + 2] + v.w * sRh[j + 3];
        }
        #pragma unroll
        for (int o = 16; o; o >>= 1) sum += __shfl_down_sync(0xffffffffu, sum, o);
        if (!lane) g_hn[(size_t)b * Hd + row] = sum;
    }

    // ---- arrival protocol: last CTA per batch finalizes ----
    __threadfence();
    __syncthreads();
    if (t == 0) {
        int old = atomicAdd(&g_cnt[b], 1);
        s_last = (old == 7);
    }
    __syncthreads();
    if (!s_last) return;
    __threadfence();   // see all 8 CTAs' g_hn writes

    // ---- phase 3: finalize ----
    float4 pre;
    if (t < 128) {
        float4 ug = ldproj4(prow, t);
        float4 hn = ((const float4*)(g_hn + (size_t)b * Hd))[t];
        pre.x = ug.x * h.x + (1.0f - ug.x) * fmaxf(hn.x + x.x, 0.0f);
        pre.y = ug.y * h.y + (1.0f - ug.y) * fmaxf(hn.y + x.y, 0.0f);
        pre.z = ug.z * h.z + (1.0f - ug.z) * fmaxf(hn.z + x.z, 0.0f);
        pre.w = ug.w * h.w + (1.0f - ug.w) * fmaxf(hn.w + x.w, 0.0f);
        float ss = pre.x * pre.x + pre.y * pre.y + pre.z * pre.z + pre.w * pre.w;
        #pragma unroll
        for (int o = 16; o; o >>= 1) ss += __shfl_down_sync(0xffffffffu, ss, o);
        if (!lane) nred[warp] = ss;
    }
    __syncthreads();
    if (t == 0) {
        float n = sqrtf(nred[0] + nred[1] + nred[2] + nred[3]);
        s_inv = 1.0f / fmaxf(n, 1e-12f);
        g_cnt[b] = 0;   // reset for next graph replay
    }
    __syncthreads();
    if (t < 128) {
        float inv = s_inv;
        float4 o4;
        o4.x = pre.x * inv; o4.y = pre.y * inv;
        o4.z = pre.z * inv; o4.w = pre.w * inv;
        ((float4*)out)[b * (Hd / 4) + t] = o4;
    }
}

extern "C" void kernel_launch(void* const* d_in, const int* in_sizes, int n_in,
                              void* d_out, int out_size)
{
    const float* inputs = (const float*)d_in[0];
    const float* hidden = (const float*)d_in[1];
    const float* assoc  = (const float*)d_in[2];
    const float* W_ih   = (const float*)d_in[3];
    const float* b_ih   = (const float*)d_in[4];
    const float* W_hh   = (const float*)d_in[5];
    const float* b_hh   = (const float*)d_in[6];
    float* out = (float*)d_out;

    gemm_mma_kernel<<<dim3(N3 / 64, Bsz / 64, 4), 128>>>(
        inputs, hidden, W_ih, W_hh, b_ih, b_hh);
    fused_mv_kernel<<<dim3(8, Bsz), 256>>>(hidden, assoc, out);
}